// round 6
// baseline (speedup 1.0000x reference)
#include <cuda_runtime.h>

#define TT   128   // timesteps
#define NN   32    // nodes
#define EE   512   // edges per timestep
#define INC  64    // input channels
#define HH   128   // hidden
#define SL   16    // seq len (steps per window)
#define WPB  32    // windows per block
#define G4   512   // 4*HH gates
#define HP4  17    // hp row stride in float4 (pad)

// ---------------- device scratch (static, no allocs) ----------------
__device__ float g_hgcn  [TT * NN * HH];        // [t][n][h]
__device__ float g_P1    [NN * TT * G4];        // [n][t][j][4]  (gate-interleaved)
__device__ float g_WihTI1[NN * HH * G4];        // [n][k][j][4]  (for p1 precompute)
__device__ float g_W1d   [NN * HH * G4 * 2];    // Whh1 dup: [n][k][j][8] = ii,ff,gg,oo
__device__ float g_W2d   [(size_t)NN * HH * G4 * 4]; // layer2: [n][k][j][16] = wi{ii,ff,gg,oo}, wh{...}
__device__ float g_WfcT  [NN * HH * HH];        // [n][k][r]

struct u64x2 { unsigned long long a, b; };

// ---------------- helpers ----------------
__device__ __forceinline__ float sigf(float x) {
    return __fdividef(1.0f, 1.0f + __expf(-x));
}
__device__ __forceinline__ float tanhfast(float x) {
    x = fminf(fmaxf(x, -15.0f), 15.0f);
    float e = __expf(2.0f * x);
    return __fdividef(e - 1.0f, e + 1.0f);
}
__device__ __forceinline__ unsigned long long pk2(float a, float b) {
    unsigned long long r;
    asm("mov.b64 %0,{%1,%2};" : "=l"(r) : "f"(a), "f"(b));
    return r;
}
__device__ __forceinline__ void upk2(unsigned long long v, float& a, float& b) {
    asm("mov.b64 {%0,%1},%2;" : "=f"(a), "=f"(b) : "l"(v));
}
__device__ __forceinline__ void fma2(unsigned long long& d, unsigned long long a, unsigned long long b) {
    asm("fma.rn.f32x2 %0,%1,%2,%0;" : "+l"(d) : "l"(a), "l"(b));
}

// ---------------- Wih1 -> gate-interleaved [n][k][j][4] (for p1_kernel) --------
__global__ void __launch_bounds__(256) tik1_kernel(const float* __restrict__ Wih1) {
    __shared__ float st[4][32][33];
    int n  = blockIdx.x;
    int jt = (blockIdx.y >> 2) * 32;
    int kt = (blockIdx.y & 3) * 32;
    const float* src = Wih1 + (size_t)n * G4 * HH;
    float4* dst = (float4*)(g_WihTI1 + (size_t)n * HH * G4);
    int tx = threadIdx.x, ty = threadIdx.y;
    #pragma unroll
    for (int g = 0; g < 4; g++)
        for (int jj = ty; jj < 32; jj += 8)
            st[g][jj][tx] = src[(g * HH + jt + jj) * HH + kt + tx];
    __syncthreads();
    for (int kk = ty; kk < 32; kk += 8) {
        float4 v;
        v.x = st[0][tx][kk]; v.y = st[1][tx][kk];
        v.z = st[2][tx][kk]; v.w = st[3][tx][kk];
        dst[(kt + kk) * HH + jt + tx] = v;
    }
}

// ---------------- Whh1 -> duplicated pairs [n][k][j][8] ------------------------
__global__ void __launch_bounds__(256) dup1_kernel(const float* __restrict__ Whh1) {
    __shared__ float st[4][32][33];
    int n  = blockIdx.x;
    int jt = (blockIdx.y >> 2) * 32;
    int kt = (blockIdx.y & 3) * 32;
    const float* src = Whh1 + (size_t)n * G4 * HH;
    float4* dst = (float4*)(g_W1d + (size_t)n * HH * G4 * 2);
    int tx = threadIdx.x, ty = threadIdx.y;
    #pragma unroll
    for (int g = 0; g < 4; g++)
        for (int jj = ty; jj < 32; jj += 8)
            st[g][jj][tx] = src[(g * HH + jt + jj) * HH + kt + tx];
    __syncthreads();
    for (int kk = ty; kk < 32; kk += 8) {
        float i = st[0][tx][kk], f = st[1][tx][kk];
        float g = st[2][tx][kk], o = st[3][tx][kk];
        int idx = ((kt + kk) * HH + jt + tx) * 2;
        dst[idx + 0] = make_float4(i, i, f, f);
        dst[idx + 1] = make_float4(g, g, o, o);
    }
}

// ---------------- Wih2+Whh2 -> combined duplicated [n][k][j][16] ---------------
__global__ void __launch_bounds__(256) dup2_kernel(
    const float* __restrict__ Wih2, const float* __restrict__ Whh2)
{
    __shared__ float si[4][32][33];
    __shared__ float sh[4][32][33];
    int n  = blockIdx.x;
    int jt = (blockIdx.y >> 2) * 32;
    int kt = (blockIdx.y & 3) * 32;
    const float* srcI = Wih2 + (size_t)n * G4 * HH;
    const float* srcH = Whh2 + (size_t)n * G4 * HH;
    float4* dst = (float4*)(g_W2d + (size_t)n * HH * G4 * 4);
    int tx = threadIdx.x, ty = threadIdx.y;
    #pragma unroll
    for (int g = 0; g < 4; g++)
        for (int jj = ty; jj < 32; jj += 8) {
            si[g][jj][tx] = srcI[(g * HH + jt + jj) * HH + kt + tx];
            sh[g][jj][tx] = srcH[(g * HH + jt + jj) * HH + kt + tx];
        }
    __syncthreads();
    for (int kk = ty; kk < 32; kk += 8) {
        int idx = ((kt + kk) * HH + jt + tx) * 4;
        float a0 = si[0][tx][kk], a1 = si[1][tx][kk], a2 = si[2][tx][kk], a3 = si[3][tx][kk];
        float b0 = sh[0][tx][kk], b1 = sh[1][tx][kk], b2 = sh[2][tx][kk], b3 = sh[3][tx][kk];
        dst[idx + 0] = make_float4(a0, a0, a1, a1);
        dst[idx + 1] = make_float4(a2, a2, a3, a3);
        dst[idx + 2] = make_float4(b0, b0, b1, b1);
        dst[idx + 3] = make_float4(b2, b2, b3, b3);
    }
}

// ---------------- plain transpose for Wfc: out[n][k][r] = in[n][r][k] ----------
__global__ void fct_kernel(const float* __restrict__ in, float* __restrict__ out) {
    int n = blockIdx.x;
    const float* src = in + (size_t)n * HH * HH;
    float* dst = out + (size_t)n * HH * HH;
    for (int i = threadIdx.x; i < HH * HH; i += blockDim.x) {
        int k = i >> 7, r = i & 127;
        dst[k * HH + r] = src[r * HH + k];
    }
}

// ---------------- 2-layer GCN per timestep, dense-adjacency formulation -------
__global__ void __launch_bounds__(256) gcn_kernel(
    const float* __restrict__ x, const int* __restrict__ ei,
    const float* __restrict__ W1, const float* __restrict__ b1,
    const float* __restrict__ W2, const float* __restrict__ b2)
{
    int t = blockIdx.x, tid = threadIdx.x;
    __shared__ float A[NN * HH];
    __shared__ float B[NN * HH];
    __shared__ float Adj[NN * NN];
    __shared__ float dinv[NN];
    __shared__ int   deg[NN];
    __shared__ int   rowS[EE];
    __shared__ int   colS[EE];

    const int* rowp = ei + (size_t)t * 2 * EE;
    const int* colp = rowp + EE;

    if (tid < NN) deg[tid] = 1;                    // self-loop
    for (int i = tid; i < NN * NN; i += 256) Adj[i] = 0.0f;
    __syncthreads();
    for (int e = tid; e < EE; e += 256) {
        int r = rowp[e], c = colp[e];
        rowS[e] = r; colS[e] = c;
        atomicAdd(&deg[c], 1);
    }
    __syncthreads();
    if (tid < NN) dinv[tid] = rsqrtf((float)deg[tid]);
    __syncthreads();
    for (int e = tid; e < EE; e += 256) {
        int r = rowS[e], c = colS[e];
        atomicAdd(&Adj[c * NN + r], dinv[r] * dinv[c]);
    }
    if (tid < NN) atomicAdd(&Adj[tid * NN + tid], dinv[tid] * dinv[tid]);
    __syncthreads();

    const float* xt = x + (size_t)t * NN * INC;
    for (int o = tid; o < NN * HH; o += 256) {
        int r = o >> 7, c = o & 127;
        float s = 0.0f;
        #pragma unroll 8
        for (int k = 0; k < INC; k++) s += xt[r * INC + k] * W1[k * HH + c];
        A[o] = s;
    }
    __syncthreads();
    for (int o = tid; o < NN * HH; o += 256) {
        int cn = o >> 7, ch = o & 127;
        float s = 0.0f;
        #pragma unroll
        for (int r = 0; r < NN; r++) s += Adj[cn * NN + r] * A[r * HH + ch];
        B[o] = fmaxf(s + b1[ch], 0.0f);
    }
    __syncthreads();
    for (int o = tid; o < NN * HH; o += 256) {
        int r = o >> 7, c = o & 127;
        float s = 0.0f;
        #pragma unroll 8
        for (int k = 0; k < HH; k++) s += B[r * HH + k] * W2[k * HH + c];
        A[o] = s;
    }
    __syncthreads();
    for (int o = tid; o < NN * HH; o += 256) {
        int cn = o >> 7, ch = o & 127;
        float s = 0.0f;
        #pragma unroll
        for (int r = 0; r < NN; r++) s += Adj[cn * NN + r] * A[r * HH + ch];
        g_hgcn[((size_t)t * NN + cn) * HH + ch] = fmaxf(s + b2[ch], 0.0f);
    }
}

// ---------------- precompute P1[n][t][j][4] = Wih1[n] @ h_gcn[t][n] -----------
__global__ void __launch_bounds__(256) p1_kernel() {
    int n = blockIdx.x, tb = blockIdx.y * 8;
    __shared__ float hs[8][HH];
    int tid = threadIdx.x;
    for (int i = tid; i < 8 * HH; i += 256) {
        int tt = i >> 7, k = i & 127;
        hs[tt][k] = g_hgcn[((size_t)(tb + tt) * NN + n) * HH + k];
    }
    __syncthreads();
    int j = tid & 127, th = tid >> 7;
    const float4* Wp = (const float4*)(g_WihTI1 + (size_t)n * HH * G4);
    float4 acc[4];
    #pragma unroll
    for (int i = 0; i < 4; i++) acc[i] = make_float4(0.f, 0.f, 0.f, 0.f);
    #pragma unroll 4
    for (int k = 0; k < HH; k++) {
        float4 wv = Wp[k * HH + j];
        #pragma unroll
        for (int i = 0; i < 4; i++) {
            float hv = hs[th * 4 + i][k];
            acc[i].x += wv.x * hv; acc[i].y += wv.y * hv;
            acc[i].z += wv.z * hv; acc[i].w += wv.w * hv;
        }
    }
    float4* out = (float4*)(g_P1 + (size_t)n * TT * G4);
    #pragma unroll
    for (int i = 0; i < 4; i++) out[(tb + th * 4 + i) * HH + j] = acc[i];
}

// ---------------- main 2-layer windowed LSTM + fc + heads ----------------
// block = (node n, chunk of 32 windows), 256 threads: (j = channel, half).
// Thread (j,half) owns channel j for windows [half*16, half*16+16).
// hp[k][w2] float4 = (h1[2w2], h1[2w2+1], h2[2w2], h2[2w2+1]).
__global__ void __launch_bounds__(256, 1) lstm_kernel(
    const float* __restrict__ bih1, const float* __restrict__ bhh1,
    const float* __restrict__ bih2, const float* __restrict__ bhh2,
    const float* __restrict__ bfc,
    const float* __restrict__ Wout0, const float* __restrict__ bout0,
    const float* __restrict__ Wout1, const float* __restrict__ bout1,
    float* __restrict__ dout)
{
    int n = blockIdx.x, chunk = blockIdx.y;
    int tid = threadIdx.x;
    int j = tid & 127, half = tid >> 7;
    int tbase = chunk * WPB;
    int w2of = half * 8;            // first pair index owned by this thread

    __shared__ __align__(16) float4 hp[HH][HP4];

    float c1[16], c2[16], h2r[16];
    #pragma unroll
    for (int l = 0; l < 16; l++) { c1[l] = 0.f; c2[l] = 0.f; h2r[l] = 0.f; }
    #pragma unroll
    for (int p = 0; p < 8; p++)
        hp[j][w2of + p] = make_float4(0.f, 0.f, 0.f, 0.f);

    unsigned long long bd1[4], bd2[4];
    #pragma unroll
    for (int g = 0; g < 4; g++) {
        float v1 = bih1[n * G4 + g * HH + j] + bhh1[n * G4 + g * HH + j];
        float v2 = bih2[n * G4 + g * HH + j] + bhh2[n * G4 + g * HH + j];
        bd1[g] = pk2(v1, v1);
        bd2[g] = pk2(v2, v2);
    }

    const u64x2* W1p = (const u64x2*)(g_W1d + (size_t)n * HH * G4 * 2);
    const u64x2* W2p = (const u64x2*)(g_W2d + (size_t)n * HH * G4 * 4);
    const float4* P1p = (const float4*)(g_P1 + (size_t)n * TT * G4);
    __syncthreads();

    for (int s = 0; s < SL; s++) {
        // ---- layer 1: acc = b1 + Whh1 @ h1old (+P1) ----
        unsigned long long acc[4][8];
        #pragma unroll
        for (int g = 0; g < 4; g++)
            #pragma unroll
            for (int p = 0; p < 8; p++) acc[g][p] = bd1[g];

        #pragma unroll 4
        for (int k = 0; k < HH; k++) {
            u64x2 wA = W1p[((k << 7) + j) * 2 + 0];   // (ii),(ff)
            u64x2 wB = W1p[((k << 7) + j) * 2 + 1];   // (gg),(oo)
            const unsigned long long* row = (const unsigned long long*)&hp[k][0];
            #pragma unroll
            for (int p = 0; p < 8; p++) {
                unsigned long long h1d = row[(w2of + p) * 2];   // LDS.64 (h1A,h1B)
                fma2(acc[0][p], wA.a, h1d);
                fma2(acc[1][p], wA.b, h1d);
                fma2(acc[2][p], wB.a, h1d);
                fma2(acc[3][p], wB.b, h1d);
            }
        }

        float h1n[16];
        #pragma unroll
        for (int p = 0; p < 8; p++) {
            float iA, iB, fA, fB, gA, gB, oA, oB;
            upk2(acc[0][p], iA, iB);
            upk2(acc[1][p], fA, fB);
            upk2(acc[2][p], gA, gB);
            upk2(acc[3][p], oA, oB);
            int wA = 2 * (w2of + p);
            int tsA = tbase + wA - (SL - 1) + s;
            int tsB = tsA + 1;
            if (tsA >= 0) {
                float4 pv = P1p[tsA * HH + j];
                iA += pv.x; fA += pv.y; gA += pv.z; oA += pv.w;
            }
            if (tsB >= 0) {
                float4 pv = P1p[tsB * HH + j];
                iB += pv.x; fB += pv.y; gB += pv.z; oB += pv.w;
            }
            int lA = 2 * p, lB = lA + 1;
            c1[lA] = sigf(fA) * c1[lA] + sigf(iA) * tanhfast(gA);
            h1n[lA] = sigf(oA) * tanhfast(c1[lA]);
            c1[lB] = sigf(fB) * c1[lB] + sigf(iB) * tanhfast(gB);
            h1n[lB] = sigf(oB) * tanhfast(c1[lB]);
        }
        __syncthreads();
        #pragma unroll
        for (int p = 0; p < 8; p++)
            ((unsigned long long*)&hp[j][w2of + p])[0] = pk2(h1n[2 * p], h1n[2 * p + 1]);
        __syncthreads();

        // ---- layer 2: acc = b2 + Wih2 @ h1new + Whh2 @ h2old ----
        #pragma unroll
        for (int g = 0; g < 4; g++)
            #pragma unroll
            for (int p = 0; p < 8; p++) acc[g][p] = bd2[g];

        #pragma unroll 2
        for (int k = 0; k < HH; k++) {
            const u64x2* wb = &W2p[((k << 7) + j) * 4];
            u64x2 wiA = wb[0];   // wi (ii),(ff)
            u64x2 wiB = wb[1];   // wi (gg),(oo)
            u64x2 whA = wb[2];   // wh (ii),(ff)
            u64x2 whB = wb[3];   // wh (gg),(oo)
            #pragma unroll
            for (int p = 0; p < 8; p++) {
                u64x2 h = *(const u64x2*)&hp[k][w2of + p];  // LDS.128 (h1 pair, h2 pair)
                fma2(acc[0][p], wiA.a, h.a); fma2(acc[0][p], whA.a, h.b);
                fma2(acc[1][p], wiA.b, h.a); fma2(acc[1][p], whA.b, h.b);
                fma2(acc[2][p], wiB.a, h.a); fma2(acc[2][p], whB.a, h.b);
                fma2(acc[3][p], wiB.b, h.a); fma2(acc[3][p], whB.b, h.b);
            }
        }

        #pragma unroll
        for (int p = 0; p < 8; p++) {
            float iA, iB, fA, fB, gA, gB, oA, oB;
            upk2(acc[0][p], iA, iB);
            upk2(acc[1][p], fA, fB);
            upk2(acc[2][p], gA, gB);
            upk2(acc[3][p], oA, oB);
            int lA = 2 * p, lB = lA + 1;
            c2[lA] = sigf(fA) * c2[lA] + sigf(iA) * tanhfast(gA);
            h2r[lA] = sigf(oA) * tanhfast(c2[lA]);
            c2[lB] = sigf(fB) * c2[lB] + sigf(iB) * tanhfast(gB);
            h2r[lB] = sigf(oB) * tanhfast(c2[lB]);
        }
        __syncthreads();
        #pragma unroll
        for (int p = 0; p < 8; p++)
            ((unsigned long long*)&hp[j][w2of + p])[1] = pk2(h2r[2 * p], h2r[2 * p + 1]);
        __syncthreads();
    }

    // ---- last = relu(h2) -> .xy slots ----
    #pragma unroll
    for (int p = 0; p < 8; p++) {
        float rA = fmaxf(h2r[2 * p], 0.0f);
        float rB = fmaxf(h2r[2 * p + 1], 0.0f);
        ((unsigned long long*)&hp[j][w2of + p])[0] = pk2(rA, rB);
    }
    __syncthreads();

    // ---- fc = Wfc @ relu(h2) + bfc ----
    {
        unsigned long long fcd[8];
        float bb = bfc[n * HH + j];
        unsigned long long bbd = pk2(bb, bb);
        #pragma unroll
        for (int p = 0; p < 8; p++) fcd[p] = bbd;
        const float* Wf = g_WfcT + (size_t)n * HH * HH;
        #pragma unroll 4
        for (int k = 0; k < HH; k++) {
            float wf = Wf[k * HH + j];
            unsigned long long wfd = pk2(wf, wf);
            const unsigned long long* row = (const unsigned long long*)&hp[k][0];
            #pragma unroll
            for (int p = 0; p < 8; p++)
                fma2(fcd[p], wfd, row[(w2of + p) * 2]);
        }
        __syncthreads();
        #pragma unroll
        for (int p = 0; p < 8; p++)
            ((unsigned long long*)&hp[j][w2of + p])[1] = fcd[p];
        __syncthreads();
    }

    // ---- heads: 32 windows x (4 + 2) outputs ----
    if (tid < 192) {
        int w = tid / 6, q = tid % 6;
        const float* wr; float bo;
        if (q < 4) { wr = Wout0 + (size_t)(n * 4 + q) * HH;       bo = bout0[n * 4 + q]; }
        else       { wr = Wout1 + (size_t)(n * 2 + (q - 4)) * HH; bo = bout1[n * 2 + (q - 4)]; }
        float s2 = bo;
        int w2 = w >> 1, odd = w & 1;
        #pragma unroll 8
        for (int k = 0; k < HH; k++) {
            float v = odd ? hp[k][w2].w : hp[k][w2].z;
            s2 += wr[k] * v;
        }
        int t = tbase + w;
        if (q < 4) dout[((size_t)t * NN + n) * 4 + q] = s2;
        else       dout[(size_t)TT * NN * 4 + ((size_t)t * NN + n) * 2 + (q - 4)] = s2;
    }
}

// ---------------- targets pass-through ----------------
__global__ void copy_y_kernel(const float* __restrict__ y, float* __restrict__ dst) {
    int i = blockIdx.x * 256 + threadIdx.x;
    if (i < TT * NN * 4) dst[i] = y[i];
}

// ---------------- launch ----------------
extern "C" void kernel_launch(void* const* d_in, const int* in_sizes, int n_in,
                              void* d_out, int out_size)
{
    const float* x     = (const float*)d_in[0];
    const int*   ei    = (const int*)  d_in[1];
    const float* y     = (const float*)d_in[3];
    const float* W1    = (const float*)d_in[4];
    const float* b1    = (const float*)d_in[5];
    const float* W2    = (const float*)d_in[6];
    const float* b2    = (const float*)d_in[7];
    const float* Wih1  = (const float*)d_in[8];
    const float* Whh1  = (const float*)d_in[9];
    const float* bih1  = (const float*)d_in[10];
    const float* bhh1  = (const float*)d_in[11];
    const float* Wih2  = (const float*)d_in[12];
    const float* Whh2  = (const float*)d_in[13];
    const float* bih2  = (const float*)d_in[14];
    const float* bhh2  = (const float*)d_in[15];
    const float* Wfc   = (const float*)d_in[16];
    const float* bfc   = (const float*)d_in[17];
    const float* Wout0 = (const float*)d_in[18];
    const float* bout0 = (const float*)d_in[19];
    const float* Wout1 = (const float*)d_in[20];
    const float* bout1 = (const float*)d_in[21];
    float* out = (float*)d_out;

    void* pWfcT;
    cudaGetSymbolAddress(&pWfcT, g_WfcT);

    tik1_kernel<<<dim3(NN, 16), dim3(32, 8)>>>(Wih1);
    dup1_kernel<<<dim3(NN, 16), dim3(32, 8)>>>(Whh1);
    dup2_kernel<<<dim3(NN, 16), dim3(32, 8)>>>(Wih2, Whh2);
    fct_kernel<<<32, 256>>>(Wfc, (float*)pWfcT);

    gcn_kernel<<<TT, 256>>>(x, ei, W1, b1, W2, b2);
    p1_kernel<<<dim3(NN, 16), 256>>>();

    lstm_kernel<<<dim3(NN, TT / WPB), 256>>>(bih1, bhh1, bih2, bhh2, bfc,
                                             Wout0, bout0, Wout1, bout1, out);

    copy_y_kernel<<<(TT * NN * 4 + 255) / 256, 256>>>(y, out + (size_t)TT * NN * 4 + (size_t)TT * NN * 2);
}

// round 7
// speedup vs baseline: 2.2849x; 2.2849x over previous
#include <cuda_runtime.h>

#define TT   128   // timesteps
#define NN   32    // nodes
#define EE   512   // edges per timestep
#define INC  64    // input channels
#define HH   128   // hidden
#define SL   16    // seq len / windows per block
#define G4   512   // 4*HH gates
#define HP   18    // padded h row stride (floats)

// ---------------- device scratch (static, no allocs) ----------------
__device__ float g_hgcn  [TT * NN * HH];   // [t][n][h]
__device__ float g_P1    [NN * TT * G4];   // [n][t][j][4]  (gate-interleaved)
__device__ float g_WihTI1[NN * HH * G4];   // [n][k][j][4]
__device__ float g_WhhTI1[NN * HH * G4];
__device__ float g_WihTI2[NN * HH * G4];
__device__ float g_WhhTI2[NN * HH * G4];
__device__ float g_WfcT  [NN * HH * HH];   // [n][k][r]

// ---------------- helpers ----------------
__device__ __forceinline__ float sigf(float x) {
    return __fdividef(1.0f, 1.0f + __expf(-x));
}
__device__ __forceinline__ float tanhfast(float x) {
    x = fminf(fmaxf(x, -15.0f), 15.0f);
    float e = __expf(2.0f * x);
    return __fdividef(e - 1.0f, e + 1.0f);
}
__device__ __forceinline__ unsigned long long pk2(float a, float b) {
    unsigned long long r;
    asm("mov.b64 %0,{%1,%2};" : "=l"(r) : "f"(a), "f"(b));
    return r;
}
__device__ __forceinline__ void upk2(unsigned long long v, float& a, float& b) {
    asm("mov.b64 {%0,%1},%2;" : "=f"(a), "=f"(b) : "l"(v));
}
__device__ __forceinline__ void fma2(unsigned long long& d, unsigned long long a, unsigned long long b) {
    asm("fma.rn.f32x2 %0,%1,%2,%0;" : "+l"(d) : "l"(a), "l"(b));
}

// ---------------- tiled transpose + gate-interleave for all 4 LSTM weights ----
// out[n][k][j*4+g] = in[n][g*128+j][k]
__global__ void __launch_bounds__(256) tik4_kernel(
    const float* __restrict__ Wih1, const float* __restrict__ Whh1,
    const float* __restrict__ Wih2, const float* __restrict__ Whh2)
{
    __shared__ float st[4][32][33];
    int n  = blockIdx.x;
    int jt = (blockIdx.y >> 2) * 32;
    int kt = (blockIdx.y & 3) * 32;
    int m  = blockIdx.z;
    const float* srcs[4] = {Wih1, Whh1, Wih2, Whh2};
    float* dsts[4] = {g_WihTI1, g_WhhTI1, g_WihTI2, g_WhhTI2};
    const float* src = srcs[m] + (size_t)n * G4 * HH;
    float4* dst = (float4*)(dsts[m] + (size_t)n * HH * G4);
    int tx = threadIdx.x, ty = threadIdx.y;

    #pragma unroll
    for (int g = 0; g < 4; g++)
        for (int jj = ty; jj < 32; jj += 8)
            st[g][jj][tx] = src[(g * HH + jt + jj) * HH + kt + tx];
    __syncthreads();
    for (int kk = ty; kk < 32; kk += 8) {
        float4 v;
        v.x = st[0][tx][kk]; v.y = st[1][tx][kk];
        v.z = st[2][tx][kk]; v.w = st[3][tx][kk];
        dst[(kt + kk) * HH + jt + tx] = v;
    }
}

// ---------------- plain transpose for Wfc: out[n][k][r] = in[n][r][k] ----------------
__global__ void fct_kernel(const float* __restrict__ in, float* __restrict__ out) {
    int n = blockIdx.x;
    const float* src = in + (size_t)n * HH * HH;
    float* dst = out + (size_t)n * HH * HH;
    for (int i = threadIdx.x; i < HH * HH; i += blockDim.x) {
        int k = i >> 7, r = i & 127;
        dst[k * HH + r] = src[r * HH + k];
    }
}

// ---------------- 2-layer GCN per timestep, dense-adjacency formulation ----------------
__global__ void __launch_bounds__(256) gcn_kernel(
    const float* __restrict__ x, const int* __restrict__ ei,
    const float* __restrict__ W1, const float* __restrict__ b1,
    const float* __restrict__ W2, const float* __restrict__ b2)
{
    int t = blockIdx.x, tid = threadIdx.x;
    __shared__ float A[NN * HH];
    __shared__ float B[NN * HH];
    __shared__ float Adj[NN * NN];
    __shared__ float dinv[NN];
    __shared__ int   deg[NN];
    __shared__ int   rowS[EE];
    __shared__ int   colS[EE];

    const int* rowp = ei + (size_t)t * 2 * EE;
    const int* colp = rowp + EE;

    if (tid < NN) deg[tid] = 1;                    // self-loop
    for (int i = tid; i < NN * NN; i += 256) Adj[i] = 0.0f;
    __syncthreads();
    for (int e = tid; e < EE; e += 256) {
        int r = rowp[e], c = colp[e];
        rowS[e] = r; colS[e] = c;
        atomicAdd(&deg[c], 1);
    }
    __syncthreads();
    if (tid < NN) dinv[tid] = rsqrtf((float)deg[tid]);
    __syncthreads();
    for (int e = tid; e < EE; e += 256) {
        int r = rowS[e], c = colS[e];
        atomicAdd(&Adj[c * NN + r], dinv[r] * dinv[c]);
    }
    if (tid < NN) atomicAdd(&Adj[tid * NN + tid], dinv[tid] * dinv[tid]);
    __syncthreads();

    // layer 1: A = x_t @ W1
    const float* xt = x + (size_t)t * NN * INC;
    for (int o = tid; o < NN * HH; o += 256) {
        int r = o >> 7, c = o & 127;
        float s = 0.0f;
        #pragma unroll 8
        for (int k = 0; k < INC; k++) s += xt[r * INC + k] * W1[k * HH + c];
        A[o] = s;
    }
    __syncthreads();
    // B = relu(Adj @ A + b1)
    for (int o = tid; o < NN * HH; o += 256) {
        int cn = o >> 7, ch = o & 127;
        float s = 0.0f;
        #pragma unroll
        for (int r = 0; r < NN; r++) s += Adj[cn * NN + r] * A[r * HH + ch];
        B[o] = fmaxf(s + b1[ch], 0.0f);
    }
    __syncthreads();
    // layer 2: A = B @ W2
    for (int o = tid; o < NN * HH; o += 256) {
        int r = o >> 7, c = o & 127;
        float s = 0.0f;
        #pragma unroll 8
        for (int k = 0; k < HH; k++) s += B[r * HH + k] * W2[k * HH + c];
        A[o] = s;
    }
    __syncthreads();
    // out = relu(Adj @ A + b2) -> global
    for (int o = tid; o < NN * HH; o += 256) {
        int cn = o >> 7, ch = o & 127;
        float s = 0.0f;
        #pragma unroll
        for (int r = 0; r < NN; r++) s += Adj[cn * NN + r] * A[r * HH + ch];
        g_hgcn[((size_t)t * NN + cn) * HH + ch] = fmaxf(s + b2[ch], 0.0f);
    }
}

// ---------------- precompute P1[n][t][j][4] = Wih1[n] @ h_gcn[t][n] ----------------
__global__ void __launch_bounds__(256) p1_kernel() {
    int n = blockIdx.x, tb = blockIdx.y * 8;
    __shared__ float hs[8][HH];
    int tid = threadIdx.x;
    for (int i = tid; i < 8 * HH; i += 256) {
        int tt = i >> 7, k = i & 127;
        hs[tt][k] = g_hgcn[((size_t)(tb + tt) * NN + n) * HH + k];
    }
    __syncthreads();
    int j = tid & 127, th = tid >> 7;
    const float4* Wp = (const float4*)(g_WihTI1 + (size_t)n * HH * G4);
    float4 acc[4];
    #pragma unroll
    for (int i = 0; i < 4; i++) acc[i] = make_float4(0.f, 0.f, 0.f, 0.f);
    #pragma unroll 4
    for (int k = 0; k < HH; k++) {
        float4 wv = Wp[k * HH + j];
        #pragma unroll
        for (int i = 0; i < 4; i++) {
            float hv = hs[th * 4 + i][k];
            acc[i].x += wv.x * hv; acc[i].y += wv.y * hv;
            acc[i].z += wv.z * hv; acc[i].w += wv.w * hv;
        }
    }
    float4* out = (float4*)(g_P1 + (size_t)n * TT * G4);
    #pragma unroll
    for (int i = 0; i < 4; i++) out[(tb + th * 4 + i) * HH + j] = acc[i];
}

// ---------------- main 2-layer windowed LSTM + fc + heads (f32x2 packed) ----------------
// block = (node n, chunk of 16 windows), 128 threads: thread j owns hidden channel j.
// Windows packed in pairs (2w, 2w+1) into f32x2 lanes. Depth-1 rotating weight prefetch.
__global__ void __launch_bounds__(128) lstm_kernel(
    const float* __restrict__ bih1, const float* __restrict__ bhh1,
    const float* __restrict__ bih2, const float* __restrict__ bhh2,
    const float* __restrict__ bfc,
    const float* __restrict__ Wout0, const float* __restrict__ bout0,
    const float* __restrict__ Wout1, const float* __restrict__ bout1,
    float* __restrict__ dout)
{
    int n = blockIdx.x, chunk = blockIdx.y;
    int j = threadIdx.x;
    int tbase = chunk * SL;

    __shared__ __align__(16) float h1s[HH][HP];
    __shared__ __align__(16) float h2s[HH][HP];

    float c1[SL], c2[SL];
    #pragma unroll
    for (int w = 0; w < SL; w++) { c1[w] = 0.f; c2[w] = 0.f; }
    #pragma unroll
    for (int w2 = 0; w2 < 8; w2++) {
        ((unsigned long long*)h1s[j])[w2] = 0ull;
        ((unsigned long long*)h2s[j])[w2] = 0ull;
    }

    unsigned long long b1d[4], b2d[4];
    #pragma unroll
    for (int g = 0; g < 4; g++) {
        float v1 = bih1[n * G4 + g * HH + j] + bhh1[n * G4 + g * HH + j];
        float v2 = bih2[n * G4 + g * HH + j] + bhh2[n * G4 + g * HH + j];
        b1d[g] = pk2(v1, v1);
        b2d[g] = pk2(v2, v2);
    }

    const float4* Wh1 = (const float4*)(g_WhhTI1 + (size_t)n * HH * G4);
    const float4* Wi2 = (const float4*)(g_WihTI2 + (size_t)n * HH * G4);
    const float4* Wh2 = (const float4*)(g_WhhTI2 + (size_t)n * HH * G4);
    const float4* P1p = (const float4*)(g_P1     + (size_t)n * TT * G4);
    __syncthreads();

    for (int s = 0; s < SL; s++) {
        // ---- layer 1 gates: b1 + P1[ts] + Whh1 @ h1 ----
        unsigned long long acc[4][8];
        #pragma unroll
        for (int g = 0; g < 4; g++)
            #pragma unroll
            for (int w2 = 0; w2 < 8; w2++) acc[g][w2] = b1d[g];

        float4 wvn = Wh1[j];                         // prefetch k=0
        #pragma unroll 4
        for (int k = 0; k < HH; k++) {
            float4 wv = wvn;
            wvn = Wh1[(((k + 1) & 127) << 7) + j];   // prefetch next (wraps harmlessly)
            unsigned long long w0 = pk2(wv.x, wv.x), w1 = pk2(wv.y, wv.y);
            unsigned long long w2d = pk2(wv.z, wv.z), w3 = pk2(wv.w, wv.w);
            const unsigned long long* hp = (const unsigned long long*)h1s[k];
            #pragma unroll
            for (int w2 = 0; w2 < 8; w2++) {
                unsigned long long hv = hp[w2];
                fma2(acc[0][w2], w0, hv);
                fma2(acc[1][w2], w1, hv);
                fma2(acc[2][w2], w2d, hv);
                fma2(acc[3][w2], w3, hv);
            }
        }

        float hn[SL];
        #pragma unroll
        for (int w2 = 0; w2 < 8; w2++) {
            float i0, i1, f0, f1, g0, g1, o0, o1;
            upk2(acc[0][w2], i0, i1);
            upk2(acc[1][w2], f0, f1);
            upk2(acc[2][w2], g0, g1);
            upk2(acc[3][w2], o0, o1);
            int wA = 2 * w2, wB = wA + 1;
            int tsA = tbase + wA - (SL - 1) + s;
            int tsB = tsA + 1;
            if (tsA >= 0) {
                float4 p = P1p[tsA * HH + j];
                i0 += p.x; f0 += p.y; g0 += p.z; o0 += p.w;
            }
            if (tsB >= 0) {
                float4 p = P1p[tsB * HH + j];
                i1 += p.x; f1 += p.y; g1 += p.z; o1 += p.w;
            }
            c1[wA] = sigf(f0) * c1[wA] + sigf(i0) * tanhfast(g0);
            hn[wA] = sigf(o0) * tanhfast(c1[wA]);
            c1[wB] = sigf(f1) * c1[wB] + sigf(i1) * tanhfast(g1);
            hn[wB] = sigf(o1) * tanhfast(c1[wB]);
        }
        __syncthreads();
        #pragma unroll
        for (int w2 = 0; w2 < 8; w2++)
            ((unsigned long long*)h1s[j])[w2] = pk2(hn[2 * w2], hn[2 * w2 + 1]);
        __syncthreads();

        // ---- layer 2 gates: b2 + Wih2 @ h1new + Whh2 @ h2 ----
        #pragma unroll
        for (int g = 0; g < 4; g++)
            #pragma unroll
            for (int w2 = 0; w2 < 8; w2++) acc[g][w2] = b2d[g];

        float4 wivn = Wi2[j];                        // prefetch k=0
        float4 whvn = Wh2[j];
        #pragma unroll 2
        for (int k = 0; k < HH; k++) {
            float4 wiv = wivn;
            float4 whv = whvn;
            int kn = (((k + 1) & 127) << 7) + j;
            wivn = Wi2[kn];
            whvn = Wh2[kn];
            unsigned long long a0 = pk2(wiv.x, wiv.x), a1 = pk2(wiv.y, wiv.y);
            unsigned long long a2 = pk2(wiv.z, wiv.z), a3 = pk2(wiv.w, wiv.w);
            unsigned long long d0 = pk2(whv.x, whv.x), d1 = pk2(whv.y, whv.y);
            unsigned long long d2 = pk2(whv.z, whv.z), d3 = pk2(whv.w, whv.w);
            const unsigned long long* hp1 = (const unsigned long long*)h1s[k];
            const unsigned long long* hp2 = (const unsigned long long*)h2s[k];
            #pragma unroll
            for (int w2 = 0; w2 < 8; w2++) {
                unsigned long long hv1 = hp1[w2];
                unsigned long long hv2 = hp2[w2];
                fma2(acc[0][w2], a0, hv1); fma2(acc[0][w2], d0, hv2);
                fma2(acc[1][w2], a1, hv1); fma2(acc[1][w2], d1, hv2);
                fma2(acc[2][w2], a2, hv1); fma2(acc[2][w2], d2, hv2);
                fma2(acc[3][w2], a3, hv1); fma2(acc[3][w2], d3, hv2);
            }
        }

        #pragma unroll
        for (int w2 = 0; w2 < 8; w2++) {
            float i0, i1, f0, f1, g0, g1, o0, o1;
            upk2(acc[0][w2], i0, i1);
            upk2(acc[1][w2], f0, f1);
            upk2(acc[2][w2], g0, g1);
            upk2(acc[3][w2], o0, o1);
            int wA = 2 * w2, wB = wA + 1;
            c2[wA] = sigf(f0) * c2[wA] + sigf(i0) * tanhfast(g0);
            hn[wA] = sigf(o0) * tanhfast(c2[wA]);
            c2[wB] = sigf(f1) * c2[wB] + sigf(i1) * tanhfast(g1);
            hn[wB] = sigf(o1) * tanhfast(c2[wB]);
        }
        __syncthreads();
        #pragma unroll
        for (int w2 = 0; w2 < 8; w2++)
            ((unsigned long long*)h2s[j])[w2] = pk2(hn[2 * w2], hn[2 * w2 + 1]);
        __syncthreads();
    }

    // ---- last = relu(h2), fc = Wfc @ last + bfc ----
    #pragma unroll
    for (int w = 0; w < SL; w++) h1s[j][w] = fmaxf(h2s[j][w], 0.0f);
    __syncthreads();

    {
        float bb = bfc[n * HH + j];
        unsigned long long fcv[8];
        unsigned long long bbd = pk2(bb, bb);
        #pragma unroll
        for (int w2 = 0; w2 < 8; w2++) fcv[w2] = bbd;
        const float* Wf = g_WfcT + (size_t)n * HH * HH;
        #pragma unroll 4
        for (int k = 0; k < HH; k++) {
            float wf = Wf[k * HH + j];
            unsigned long long wfd = pk2(wf, wf);
            const unsigned long long* hr = (const unsigned long long*)h1s[k];
            #pragma unroll
            for (int w2 = 0; w2 < 8; w2++) fma2(fcv[w2], wfd, hr[w2]);
        }
        __syncthreads();
        #pragma unroll
        for (int w2 = 0; w2 < 8; w2++)
            ((unsigned long long*)h2s[j])[w2] = fcv[w2];
        __syncthreads();
    }

    // ---- heads: 16 windows x (4 + 2) outputs ----
    if (j < 96) {
        int w = j / 6, q = j % 6;
        const float* wr; float bo;
        if (q < 4) { wr = Wout0 + (size_t)(n * 4 + q) * HH;       bo = bout0[n * 4 + q]; }
        else       { wr = Wout1 + (size_t)(n * 2 + (q - 4)) * HH; bo = bout1[n * 2 + (q - 4)]; }
        float s2 = bo;
        #pragma unroll 8
        for (int k = 0; k < HH; k++) s2 += wr[k] * h2s[k][w];
        int t = tbase + w;
        if (q < 4) dout[((size_t)t * NN + n) * 4 + q] = s2;
        else       dout[(size_t)TT * NN * 4 + ((size_t)t * NN + n) * 2 + (q - 4)] = s2;
    }
}

// ---------------- targets pass-through ----------------
__global__ void copy_y_kernel(const float* __restrict__ y, float* __restrict__ dst) {
    int i = blockIdx.x * 256 + threadIdx.x;
    if (i < TT * NN * 4) dst[i] = y[i];
}

// ---------------- launch ----------------
extern "C" void kernel_launch(void* const* d_in, const int* in_sizes, int n_in,
                              void* d_out, int out_size)
{
    const float* x     = (const float*)d_in[0];
    const int*   ei    = (const int*)  d_in[1];
    const float* y     = (const float*)d_in[3];
    const float* W1    = (const float*)d_in[4];
    const float* b1    = (const float*)d_in[5];
    const float* W2    = (const float*)d_in[6];
    const float* b2    = (const float*)d_in[7];
    const float* Wih1  = (const float*)d_in[8];
    const float* Whh1  = (const float*)d_in[9];
    const float* bih1  = (const float*)d_in[10];
    const float* bhh1  = (const float*)d_in[11];
    const float* Wih2  = (const float*)d_in[12];
    const float* Whh2  = (const float*)d_in[13];
    const float* bih2  = (const float*)d_in[14];
    const float* bhh2  = (const float*)d_in[15];
    const float* Wfc   = (const float*)d_in[16];
    const float* bfc   = (const float*)d_in[17];
    const float* Wout0 = (const float*)d_in[18];
    const float* bout0 = (const float*)d_in[19];
    const float* Wout1 = (const float*)d_in[20];
    const float* bout1 = (const float*)d_in[21];
    float* out = (float*)d_out;

    void* pWfcT;
    cudaGetSymbolAddress(&pWfcT, g_WfcT);

    // launch order arranged so lstm_kernel is launch index 5 (ncu -s 5 -c 1 captures it)
    tik4_kernel<<<dim3(NN, 16, 4), dim3(32, 8)>>>(Wih1, Whh1, Wih2, Whh2);   // 0
    fct_kernel<<<32, 256>>>(Wfc, (float*)pWfcT);                             // 1
    gcn_kernel<<<TT, 256>>>(x, ei, W1, b1, W2, b2);                          // 2
    p1_kernel<<<dim3(NN, 16), 256>>>();                                      // 3
    copy_y_kernel<<<(TT * NN * 4 + 255) / 256, 256>>>(y, out + (size_t)TT * NN * 4 + (size_t)TT * NN * 2);  // 4
    lstm_kernel<<<dim3(NN, TT / SL), HH>>>(bih1, bhh1, bih2, bhh2, bfc,
                                           Wout0, bout0, Wout1, bout1, out); // 5
}